// round 6
// baseline (speedup 1.0000x reference)
#include <cuda_runtime.h>

#define NS   128     // samples per ray
#define HD   64      // hidden dim
#define GRD  64      // density grid

// ---- packed f32x2 helpers (Blackwell-only: ptxas never emits these from C++) ----
__device__ __forceinline__ unsigned long long pack_f32x2(float x, float y) {
    unsigned long long r;
    asm("mov.b64 %0, {%1, %2};" : "=l"(r) : "r"(__float_as_uint(x)), "r"(__float_as_uint(y)));
    return r;
}
__device__ __forceinline__ void unpack_f32x2(unsigned long long v, float& x, float& y) {
    unsigned lo, hi;
    asm("mov.b64 {%0, %1}, %2;" : "=r"(lo), "=r"(hi) : "l"(v));
    x = __uint_as_float(lo);
    y = __uint_as_float(hi);
}
__device__ __forceinline__ unsigned long long ffma2(unsigned long long a,
                                                    unsigned long long b,
                                                    unsigned long long c) {
    unsigned long long d;
    asm("fma.rn.f32x2 %0, %1, %2, %3;" : "=l"(d) : "l"(a), "l"(b), "l"(c));
    return d;
}

__global__ void __launch_bounds__(NS, 4)
raymarch_mlp_kernel(const float* __restrict__ rays_o,
                    const float* __restrict__ rays_d,
                    const float* __restrict__ nearp,
                    const float* __restrict__ farp,
                    const float* __restrict__ jitter,
                    const float* __restrict__ density,
                    const float* __restrict__ W1,  const float* __restrict__ b1,
                    const float* __restrict__ W2,  const float* __restrict__ b2,
                    const float* __restrict__ Wsig, const float* __restrict__ bsig,
                    const float* __restrict__ Wrgb, const float* __restrict__ brgb,
                    float* __restrict__ out)
{
    __shared__ __align__(16) float  W2s[HD * HD];   // 16 KB
    __shared__ __align__(16) float4 h1pack[HD];     // (W1x, W1y, W1z, b1) per hidden unit
    __shared__ __align__(16) float4 heads[HD];      // (Wsig, Wrgb0, Wrgb1, Wrgb2) per hidden unit
    __shared__ __align__(16) float  b2s[HD];
    __shared__ float alpha_sh[NS];                  // alpha, then overwritten with w
    __shared__ float red0[NS], red1[NS], red2[NS];
    __shared__ float nohit_sh;

    const int tid = threadIdx.x;
    const int ray = blockIdx.x;

    // ---- cooperative weight staging (broadcast-friendly layouts) ----
    {
        const float4* W2v = (const float4*)W2;
        float4* W2sv = (float4*)W2s;
        #pragma unroll
        for (int i = 0; i < (HD * HD / 4) / NS; i++)
            W2sv[tid + i * NS] = W2v[tid + i * NS];
        if (tid < HD) {
            h1pack[tid] = make_float4(W1[tid], W1[HD + tid], W1[2 * HD + tid], b1[tid]);
            heads[tid]  = make_float4(Wsig[tid], Wrgb[3 * tid], Wrgb[3 * tid + 1], Wrgb[3 * tid + 2]);
            b2s[tid]    = b2[tid];
        }
    }
    __syncthreads();

    // ---- ray / sample setup ----
    const float nv   = __ldg(&nearp[ray]);
    const float fv   = __ldg(&farp[ray]);
    const float step = (fv - nv) * (1.0f / (float)NS);
    const float ox = __ldg(&rays_o[ray * 3 + 0]);
    const float oy = __ldg(&rays_o[ray * 3 + 1]);
    const float oz = __ldg(&rays_o[ray * 3 + 2]);
    const float dx = __ldg(&rays_d[ray * 3 + 0]);
    const float dy = __ldg(&rays_d[ray * 3 + 1]);
    const float dz = __ldg(&rays_d[ray * 3 + 2]);

    const float z = nv + (float)tid * step;

    // occupancy test at the unjittered position (matches reference pts0)
    const float qx = ox + z * dx;
    const float qy = oy + z * dy;
    const float qz = oz + z * dz;
    // u = (p - aabb_min) / (aabb_max - aabb_min); idx = floor(u * 64)
    const float fx = floorf(((qx + 1.25f) / 2.5f) * 64.0f);
    const float fy = floorf(((qy + 1.55f) / 2.5f) * 64.0f);
    const float fz = floorf(((qz + 1.25f) / 2.5f) * 64.0f);
    const bool inb = (fx >= 0.0f) & (fx < 64.0f) &
                     (fy >= 0.0f) & (fy < 64.0f) &
                     (fz >= 0.0f) & (fz < 64.0f);
    bool mask = false;
    if (inb) {
        const int ix = (int)fx, iy = (int)fy, iz = (int)fz;
        mask = __ldg(&density[(ix * GRD + iy) * GRD + iz]) > 0.5f;
    }

    // z_vals = where(mask, z, 0) + jitter*step ; pts at jittered position
    const float jit = __ldg(&jitter[ray * NS + tid]);
    const float zv  = (mask ? z : 0.0f) + jit * step;
    const float px = ox + zv * dx;
    const float py = oy + zv * dy;
    const float pz = oz + zv * dz;

    float alpha = 0.0f, r0 = 0.0f, r1 = 0.0f, r2 = 0.0f;

    // Warp-level empty-space skip: trailing out-of-AABB samples make whole
    // warps fully masked — skip the entire MLP for them.
    const unsigned bal = __ballot_sync(0xffffffffu, mask);
    if (bal) {
        // ---- layer 2 accumulators (f32x2-packed), init with b2 ----
        unsigned long long acc[HD / 2];
        {
            const unsigned long long* b2p = (const unsigned long long*)b2s;
            #pragma unroll
            for (int j = 0; j < HD / 2; j++) acc[j] = b2p[j];
        }

        // ---- fused layer1 (on the fly) + layer2 (f32x2 FMA) ----
        #pragma unroll 1
        for (int k = 0; k < HD; k++) {
            const float4 wp = h1pack[k];
            float h1 = fmaf(wp.x, px, fmaf(wp.y, py, fmaf(wp.z, pz, wp.w)));
            h1 = fmaxf(h1, 0.0f);
            const unsigned long long h1p = pack_f32x2(h1, h1);
            const ulonglong2* row = (const ulonglong2*)(W2s + k * HD);
            #pragma unroll
            for (int j = 0; j < HD / 4; j++) {
                const ulonglong2 v = row[j];
                acc[2 * j]     = ffma2(h1p, v.x, acc[2 * j]);
                acc[2 * j + 1] = ffma2(h1p, v.y, acc[2 * j + 1]);
            }
        }

        // ---- heads: sigma + rgb ----
        float sig = __ldg(bsig);
        float c0 = __ldg(&brgb[0]);
        float c1 = __ldg(&brgb[1]);
        float c2 = __ldg(&brgb[2]);
        #pragma unroll
        for (int j = 0; j < HD / 2; j++) {
            float a, b;
            unpack_f32x2(acc[j], a, b);
            a = fmaxf(a, 0.0f);
            b = fmaxf(b, 0.0f);
            const float4 hA = heads[2 * j];
            const float4 hB = heads[2 * j + 1];
            sig = fmaf(a, hA.x, fmaf(b, hB.x, sig));
            c0  = fmaf(a, hA.y, fmaf(b, hB.y, c0));
            c1  = fmaf(a, hA.z, fmaf(b, hB.z, c1));
            c2  = fmaf(a, hA.w, fmaf(b, hB.w, c2));
        }

        if (mask) {
            const float tau = fmaxf(sig, 0.0f) * step;
            alpha = 1.0f - expf(-tau);
            r0 = 1.0f / (1.0f + expf(-c0));
            r1 = 1.0f / (1.0f + expf(-c1));
            r2 = 1.0f / (1.0f + expf(-c2));
        }
        // !mask lanes keep alpha=0, rgb=0 (== reference sigma=-1000, rgb=0)
    }

    // ---- composite: sequential transmittance scan, then tree-reduce ----
    alpha_sh[tid] = alpha;
    __syncthreads();

    if (tid == 0) {
        float t = 1.0f;
        #pragma unroll 4
        for (int i = 0; i < NS; i++) {
            const float a = alpha_sh[i];
            alpha_sh[i] = a * t;                 // w_i = alpha_i * trans_i
            t = t * (1.0f - a + 1e-10f);
        }
        nohit_sh = t;                            // trans after all samples
    }
    __syncthreads();

    const float w = alpha_sh[tid];
    red0[tid] = w * r0;
    red1[tid] = w * r1;
    red2[tid] = w * r2;
    __syncthreads();

    #pragma unroll
    for (int off = NS / 2; off > 0; off >>= 1) {
        if (tid < off) {
            red0[tid] += red0[tid + off];
            red1[tid] += red1[tid + off];
            red2[tid] += red2[tid + off];
        }
        __syncthreads();
    }

    if (tid == 0) {
        const float nh = nohit_sh;               // white background
        out[ray * 3 + 0] = red0[0] + nh;
        out[ray * 3 + 1] = red1[0] + nh;
        out[ray * 3 + 2] = red2[0] + nh;
    }
}

extern "C" void kernel_launch(void* const* d_in, const int* in_sizes, int n_in,
                              void* d_out, int out_size) {
    const float* rays_o  = (const float*)d_in[0];
    const float* rays_d  = (const float*)d_in[1];
    const float* nearp   = (const float*)d_in[2];
    const float* farp    = (const float*)d_in[3];
    const float* jitter  = (const float*)d_in[4];
    const float* density = (const float*)d_in[5];
    const float* W1      = (const float*)d_in[6];
    const float* b1      = (const float*)d_in[7];
    const float* W2      = (const float*)d_in[8];
    const float* b2      = (const float*)d_in[9];
    const float* Wsig    = (const float*)d_in[10];
    const float* bsig    = (const float*)d_in[11];
    const float* Wrgb    = (const float*)d_in[12];
    const float* brgb    = (const float*)d_in[13];
    float* out = (float*)d_out;

    const int N = in_sizes[2];   // number of rays (near has N elements)
    raymarch_mlp_kernel<<<N, NS>>>(rays_o, rays_d, nearp, farp, jitter, density,
                                   W1, b1, W2, b2, Wsig, bsig, Wrgb, brgb, out);
}

// round 9
// speedup vs baseline: 1.0769x; 1.0769x over previous
#include <cuda_runtime.h>

#define NS   128     // samples per ray
#define HD   64      // hidden dim
#define GRD  64      // density grid

// ---- dynamic smem layout (bytes) ----
#define SM_W2     0                      // float[64*64]      16384
#define SM_H1     16384                  // float[64*128]     32768
#define SM_HEADS  49152                  // float4[64]         1024
#define SM_B2     50176                  // float[64]           256
#define SM_ALPHA  50432                  // float[128]          512
#define SM_R0     50944                  // float[128]          512
#define SM_R1     51456
#define SM_R2     51968
#define SM_MASK   52480                  // uchar[128]          128
#define SM_NOHIT  52608                  // float
#define SMEM_SZ   52736

__constant__ float c_W1[4 * HD];         // [0:64)=W1x [64:128)=W1y [128:192)=W1z [192:256)=b1

// ---- packed f32x2 helpers (Blackwell-only: ptxas never emits FFMA2 from C++) ----
__device__ __forceinline__ unsigned long long pack_f32x2(float x, float y) {
    unsigned long long r;
    asm("mov.b64 %0, {%1, %2};" : "=l"(r) : "r"(__float_as_uint(x)), "r"(__float_as_uint(y)));
    return r;
}
__device__ __forceinline__ void unpack_f32x2(unsigned long long v, float& x, float& y) {
    unsigned lo, hi;
    asm("mov.b64 {%0, %1}, %2;" : "=r"(lo), "=r"(hi) : "l"(v));
    x = __uint_as_float(lo);
    y = __uint_as_float(hi);
}
__device__ __forceinline__ unsigned long long ffma2(unsigned long long a,
                                                    unsigned long long b,
                                                    unsigned long long c) {
    unsigned long long d;
    asm("fma.rn.f32x2 %0, %1, %2, %3;" : "=l"(d) : "l"(a), "l"(b), "l"(c));
    return d;
}

__global__ void __launch_bounds__(NS, 4)
raymarch_mlp_kernel(const float* __restrict__ rays_o,
                    const float* __restrict__ rays_d,
                    const float* __restrict__ nearp,
                    const float* __restrict__ farp,
                    const float* __restrict__ jitter,
                    const float* __restrict__ density,
                    const float* __restrict__ W2,  const float* __restrict__ b2,
                    const float* __restrict__ Wsig, const float* __restrict__ bsig,
                    const float* __restrict__ Wrgb, const float* __restrict__ brgb,
                    float* __restrict__ out)
{
    extern __shared__ char smraw[];
    float*  W2s      = (float*)(smraw + SM_W2);      // [k][j]
    float*  H1s      = (float*)(smraw + SM_H1);      // [k][sample]
    float4* heads_s  = (float4*)(smraw + SM_HEADS);  // (Wsig, Wrgb0, Wrgb1, Wrgb2) per hidden unit
    float*  b2s      = (float*)(smraw + SM_B2);
    float*  alpha_sh = (float*)(smraw + SM_ALPHA);
    float*  r0s      = (float*)(smraw + SM_R0);
    float*  r1s      = (float*)(smraw + SM_R1);
    float*  r2s      = (float*)(smraw + SM_R2);
    unsigned char* mask_sh = (unsigned char*)(smraw + SM_MASK);
    float*  nohit_sh = (float*)(smraw + SM_NOHIT);

    const int tid  = threadIdx.x;
    const int lane = tid & 31;
    const int ray  = blockIdx.x;

    // ---- cooperative weight staging ----
    {
        const float4* W2v = (const float4*)W2;
        float4* dst = (float4*)W2s;
        #pragma unroll
        for (int i = 0; i < (HD * HD / 4) / NS; i++)
            dst[tid + i * NS] = W2v[tid + i * NS];
        if (tid < HD) {
            heads_s[tid] = make_float4(Wsig[tid], Wrgb[3 * tid], Wrgb[3 * tid + 1], Wrgb[3 * tid + 2]);
            b2s[tid]     = b2[tid];
        }
    }
    __syncthreads();

    // ---- per-sample setup (sample index == tid) ----
    const float nv   = __ldg(&nearp[ray]);
    const float fv   = __ldg(&farp[ray]);
    const float step = (fv - nv) * (1.0f / (float)NS);
    const float ox = __ldg(&rays_o[ray * 3 + 0]);
    const float oy = __ldg(&rays_o[ray * 3 + 1]);
    const float oz = __ldg(&rays_o[ray * 3 + 2]);
    const float dx = __ldg(&rays_d[ray * 3 + 0]);
    const float dy = __ldg(&rays_d[ray * 3 + 1]);
    const float dz = __ldg(&rays_d[ray * 3 + 2]);

    const float z = nv + (float)tid * step;

    // occupancy test at the unjittered position (matches reference pts0)
    const float qx = ox + z * dx;
    const float qy = oy + z * dy;
    const float qz = oz + z * dz;
    const float fx = floorf(((qx + 1.25f) / 2.5f) * 64.0f);
    const float fy = floorf(((qy + 1.55f) / 2.5f) * 64.0f);
    const float fz = floorf(((qz + 1.25f) / 2.5f) * 64.0f);
    const bool inb = (fx >= 0.0f) & (fx < 64.0f) &
                     (fy >= 0.0f) & (fy < 64.0f) &
                     (fz >= 0.0f) & (fz < 64.0f);
    bool mask = false;
    if (inb) {
        const int ix = (int)fx, iy = (int)fy, iz = (int)fz;
        mask = __ldg(&density[(ix * GRD + iy) * GRD + iz]) > 0.5f;
    }
    mask_sh[tid] = mask ? 1 : 0;

    const float jit = __ldg(&jitter[ray * NS + tid]);
    const float zv  = (mask ? z : 0.0f) + jit * step;
    const float px = ox + zv * dx;
    const float py = oy + zv * dy;
    const float pz = oz + zv * dz;

    // Warp-level empty-space skip (bal is warp-uniform)
    const unsigned bal = __ballot_sync(0xffffffffu, mask);
    if (bal) {
        // ---- phase A: h1 for own sample, W1 via constant port (no L1TEX traffic) ----
        #pragma unroll 4
        for (int k = 0; k < HD; k++) {
            float h1 = fmaf(c_W1[k], px,
                       fmaf(c_W1[HD + k], py,
                       fmaf(c_W1[2 * HD + k], pz, c_W1[3 * HD + k])));
            H1s[k * NS + tid] = fmaxf(h1, 0.0f);
        }
        __syncwarp();   // orders H1s/mask_sh writes vs. cross-lane reads below (same warp)

        // ---- phase B: register-tiled layer 2 (8 samples x 8 outputs per thread) ----
        const int sg    = lane >> 3;              // sample group [0,4)
        const int jg    = lane & 7;               // output group [0,8)
        const int sbase = (tid & ~31) + (sg << 3);// first sample of this thread's tile
        const int jb    = jg << 3;                // first output channel

        unsigned long long acc[4][8];             // [sample-pair][j], f32x2 packs (s, s+1)
        {
            const float* b2p = &b2s[jb];
            #pragma unroll
            for (int j = 0; j < 8; j++) {
                const unsigned long long d = pack_f32x2(b2p[j], b2p[j]);
                acc[0][j] = d; acc[1][j] = d; acc[2][j] = d; acc[3][j] = d;
            }
        }

        const float* h1p = &H1s[sbase];
        const float* w2p = &W2s[jb];
        #pragma unroll 2
        for (int k = 0; k < HD; k++) {
            const ulonglong2 ha = *(const ulonglong2*)h1p;        // samples +0..3 (paired)
            const ulonglong2 hb = *(const ulonglong2*)(h1p + 4);  // samples +4..7
            const float4 wa = *(const float4*)w2p;
            const float4 wb = *(const float4*)(w2p + 4);
            const float wv[8] = {wa.x, wa.y, wa.z, wa.w, wb.x, wb.y, wb.z, wb.w};
            #pragma unroll
            for (int j = 0; j < 8; j++) {
                const unsigned long long wd = pack_f32x2(wv[j], wv[j]);
                acc[0][j] = ffma2(ha.x, wd, acc[0][j]);
                acc[1][j] = ffma2(ha.y, wd, acc[1][j]);
                acc[2][j] = ffma2(hb.x, wd, acc[2][j]);
                acc[3][j] = ffma2(hb.y, wd, acc[3][j]);
            }
            h1p += NS; w2p += HD;
        }

        // ---- heads: per-thread partials over its 8 j, then octet butterfly ----
        float ps[8], p0[8], p1[8], p2[8];
        #pragma unroll
        for (int s = 0; s < 8; s++) { ps[s] = 0.f; p0[s] = 0.f; p1[s] = 0.f; p2[s] = 0.f; }

        #pragma unroll
        for (int j = 0; j < 8; j++) {
            const float4 hc = heads_s[jb + j];
            #pragma unroll
            for (int s2 = 0; s2 < 4; s2++) {
                float a, b;
                unpack_f32x2(acc[s2][j], a, b);
                a = fmaxf(a, 0.0f);
                b = fmaxf(b, 0.0f);
                ps[2 * s2]     = fmaf(a, hc.x, ps[2 * s2]);
                p0[2 * s2]     = fmaf(a, hc.y, p0[2 * s2]);
                p1[2 * s2]     = fmaf(a, hc.z, p1[2 * s2]);
                p2[2 * s2]     = fmaf(a, hc.w, p2[2 * s2]);
                ps[2 * s2 + 1] = fmaf(b, hc.x, ps[2 * s2 + 1]);
                p0[2 * s2 + 1] = fmaf(b, hc.y, p0[2 * s2 + 1]);
                p1[2 * s2 + 1] = fmaf(b, hc.z, p1[2 * s2 + 1]);
                p2[2 * s2 + 1] = fmaf(b, hc.w, p2[2 * s2 + 1]);
            }
        }

        #pragma unroll
        for (int m = 1; m < 8; m <<= 1) {
            #pragma unroll
            for (int s = 0; s < 8; s++) {
                ps[s] += __shfl_xor_sync(0xffffffffu, ps[s], m);
                p0[s] += __shfl_xor_sync(0xffffffffu, p0[s], m);
                p1[s] += __shfl_xor_sync(0xffffffffu, p1[s], m);
                p2[s] += __shfl_xor_sync(0xffffffffu, p2[s], m);
            }
        }

        if (jg == 0) {
            const float bs = __ldg(bsig);
            const float g0 = __ldg(&brgb[0]);
            const float g1 = __ldg(&brgb[1]);
            const float g2 = __ldg(&brgb[2]);
            #pragma unroll
            for (int s = 0; s < 8; s++) {
                const int samp = sbase + s;
                float al = 0.f, q0 = 0.f, q1 = 0.f, q2 = 0.f;
                if (mask_sh[samp]) {
                    const float tau = fmaxf(ps[s] + bs, 0.0f) * step;
                    al = 1.0f - expf(-tau);
                    q0 = 1.0f / (1.0f + expf(-(p0[s] + g0)));
                    q1 = 1.0f / (1.0f + expf(-(p1[s] + g1)));
                    q2 = 1.0f / (1.0f + expf(-(p2[s] + g2)));
                }
                alpha_sh[samp] = al;
                r0s[samp] = q0; r1s[samp] = q1; r2s[samp] = q2;
            }
        }
    } else {
        // fully-masked warp: all its samples contribute nothing
        alpha_sh[tid] = 0.f;
        r0s[tid] = 0.f; r1s[tid] = 0.f; r2s[tid] = 0.f;
    }

    // ---- composite: sequential transmittance scan, then tree-reduce ----
    __syncthreads();

    if (tid == 0) {
        float t = 1.0f;
        #pragma unroll 4
        for (int i = 0; i < NS; i++) {
            const float a = alpha_sh[i];
            alpha_sh[i] = a * t;                 // w_i = alpha_i * trans_i
            t = t * (1.0f - a + 1e-10f);
        }
        *nohit_sh = t;
    }
    __syncthreads();

    {
        const float w = alpha_sh[tid];
        r0s[tid] *= w;
        r1s[tid] *= w;
        r2s[tid] *= w;
    }
    __syncthreads();

    #pragma unroll
    for (int off = NS / 2; off > 0; off >>= 1) {
        if (tid < off) {
            r0s[tid] += r0s[tid + off];
            r1s[tid] += r1s[tid + off];
            r2s[tid] += r2s[tid + off];
        }
        __syncthreads();
    }

    if (tid == 0) {
        const float nh = *nohit_sh;              // white background
        out[ray * 3 + 0] = r0s[0] + nh;
        out[ray * 3 + 1] = r1s[0] + nh;
        out[ray * 3 + 2] = r2s[0] + nh;
    }
}

extern "C" void kernel_launch(void* const* d_in, const int* in_sizes, int n_in,
                              void* d_out, int out_size) {
    const float* rays_o  = (const float*)d_in[0];
    const float* rays_d  = (const float*)d_in[1];
    const float* nearp   = (const float*)d_in[2];
    const float* farp    = (const float*)d_in[3];
    const float* jitter  = (const float*)d_in[4];
    const float* density = (const float*)d_in[5];
    const float* W1      = (const float*)d_in[6];
    const float* b1      = (const float*)d_in[7];
    const float* W2      = (const float*)d_in[8];
    const float* b2      = (const float*)d_in[9];
    const float* Wsig    = (const float*)d_in[10];
    const float* bsig    = (const float*)d_in[11];
    const float* Wrgb    = (const float*)d_in[12];
    const float* brgb    = (const float*)d_in[13];
    float* out = (float*)d_out;

    // W1 (3*64 floats) + b1 (64 floats) -> constant bank (graph-capturable D2D copies)
    cudaMemcpyToSymbolAsync(c_W1, W1, 3 * HD * sizeof(float), 0,
                            cudaMemcpyDeviceToDevice, 0);
    cudaMemcpyToSymbolAsync(c_W1, b1, HD * sizeof(float), 3 * HD * sizeof(float),
                            cudaMemcpyDeviceToDevice, 0);

    static int attr_set = 0;
    if (!attr_set) {
        cudaFuncSetAttribute(raymarch_mlp_kernel,
                             cudaFuncAttributeMaxDynamicSharedMemorySize, SMEM_SZ);
        attr_set = 1;
    }

    const int N = in_sizes[2];   // number of rays (near has N elements)
    raymarch_mlp_kernel<<<N, NS, SMEM_SZ>>>(rays_o, rays_d, nearp, farp, jitter, density,
                                            W2, b2, Wsig, bsig, Wrgb, brgb, out);
}

// round 11
// speedup vs baseline: 2.2328x; 2.0734x over previous
#include <cuda_runtime.h>
#include <cstdint>

#define NS   128     // samples per ray == block threads
#define HD   64      // hidden dim
#define GRD  64
#define H1STR 68     // H1 row stride in floats (conflict-free, 16B-aligned)

// ---- dynamic smem layout (bytes) ----
#define OFF_B     0        // uint32 Bfrag[4096]  (W2 tf32 in mma fragment order) 16384
#define OFF_H1    16384    // uint32 H1[128*68]   34816
#define OFF_HEADS 51200    // float4[64] (Wsig, Wr, Wg, Wb) per channel  1024
#define OFF_B2    52224    // float[64]
#define OFF_ALPHA 52480    // float[128]
#define OFF_R0    52992    // float[128]
#define OFF_R1    53504
#define OFF_R2    54016
#define OFF_MASK  54528    // uchar[128]
#define OFF_NOHIT 54656    // float
#define SMEM_SZ   54784

// W1 quads (x,y,z,b1) per hidden unit -> uniform constant-port reads in phase A
__constant__ __align__(16) float c_W1q[4 * HD];
__device__  __align__(16) float g_W1q[4 * HD];

__global__ void prep_kernel(const float* W1, const float* b1) {
    const int j = threadIdx.x;       // 64 threads
    g_W1q[4 * j + 0] = W1[j];
    g_W1q[4 * j + 1] = W1[HD + j];
    g_W1q[4 * j + 2] = W1[2 * HD + j];
    g_W1q[4 * j + 3] = b1[j];
}

__device__ __forceinline__ uint32_t f2tf32(float f) {
    uint32_t r;
    asm("cvt.rna.tf32.f32 %0, %1;" : "=r"(r) : "f"(f));
    return r;
}

// m16n8k8 tf32 MMA (sm_80+ feature set -> valid on plain sm_103 target)
__device__ __forceinline__ void mma_tf32(float* c,
                                         uint32_t a0, uint32_t a1, uint32_t a2, uint32_t a3,
                                         uint32_t b0, uint32_t b1) {
    asm volatile(
        "mma.sync.aligned.m16n8k8.row.col.f32.tf32.tf32.f32 "
        "{%0,%1,%2,%3}, {%4,%5,%6,%7}, {%8,%9}, {%0,%1,%2,%3};"
        : "+f"(c[0]), "+f"(c[1]), "+f"(c[2]), "+f"(c[3])
        : "r"(a0), "r"(a1), "r"(a2), "r"(a3), "r"(b0), "r"(b1));
}

__global__ void __launch_bounds__(NS, 4)
raymarch_mma_kernel(const float* __restrict__ rays_o,
                    const float* __restrict__ rays_d,
                    const float* __restrict__ nearp,
                    const float* __restrict__ farp,
                    const float* __restrict__ jitter,
                    const float* __restrict__ density,
                    const float* __restrict__ W2,  const float* __restrict__ b2,
                    const float* __restrict__ Wsig, const float* __restrict__ bsig,
                    const float* __restrict__ Wrgb, const float* __restrict__ brgb,
                    float* __restrict__ out)
{
    extern __shared__ unsigned char sm[];
    uint32_t* Bfrag   = (uint32_t*)(sm + OFF_B);
    uint32_t* H1u     = (uint32_t*)(sm + OFF_H1);
    float4*   heads_s = (float4*)(sm + OFF_HEADS);
    float*    b2s     = (float*)(sm + OFF_B2);
    float*    alpha_sh= (float*)(sm + OFF_ALPHA);
    float*    r0s     = (float*)(sm + OFF_R0);
    float*    r1s     = (float*)(sm + OFF_R1);
    float*    r2s     = (float*)(sm + OFF_R2);
    unsigned char* mask_sh = (unsigned char*)(sm + OFF_MASK);
    float*    nohit_sh = (float*)(sm + OFF_NOHIT);

    const int tid  = threadIdx.x;
    const int lane = tid & 31;
    const int wid  = tid >> 5;
    const int g    = lane >> 2;      // mma groupID (row-in-tile / col-in-B-tile)
    const int tig  = lane & 3;       // thread-in-group
    const int sbase = wid * 32;      // this warp's first sample
    const int ray  = blockIdx.x;

    // ---- one-time staging: W2 -> tf32 fragment order; heads/b2 -> smem ----
    // element (k, j): kt=k>>3, r=k&7; nt=j>>3, gg=j&7; owner lane = gg*4 + (r&3);
    // b-half = r>>2.  pos = ((kt*8+nt)*32 + lane)*2 + half
    #pragma unroll
    for (int i = 0; i < (HD * HD) / NS; i++) {
        const int idx = tid + i * NS;                  // coalesced read
        const int k = idx >> 6, j = idx & 63;
        const int pos = ((((k >> 3) << 3) + (j >> 3)) * 32 + ((j & 7) << 2) + (k & 3)) * 2
                        + ((k & 7) >> 2);
        Bfrag[pos] = f2tf32(W2[idx]);
    }
    if (tid < HD) {
        heads_s[tid] = make_float4(Wsig[tid], Wrgb[3 * tid], Wrgb[3 * tid + 1], Wrgb[3 * tid + 2]);
        b2s[tid]     = b2[tid];
    }
    __syncthreads();

    // ---- per-sample setup (sample == tid) ----
    const float nv = __ldg(&nearp[ray]);
    const float fv = __ldg(&farp[ray]);
    const float step = (fv - nv) * (1.0f / (float)NS);
    const float ox = __ldg(&rays_o[ray * 3 + 0]);
    const float oy = __ldg(&rays_o[ray * 3 + 1]);
    const float oz = __ldg(&rays_o[ray * 3 + 2]);
    const float dx = __ldg(&rays_d[ray * 3 + 0]);
    const float dy = __ldg(&rays_d[ray * 3 + 1]);
    const float dz = __ldg(&rays_d[ray * 3 + 2]);
    const float z  = nv + (float)tid * step;

    const float qx = ox + z * dx, qy = oy + z * dy, qz = oz + z * dz;
    const float fx = floorf(((qx + 1.25f) / 2.5f) * 64.0f);
    const float fy = floorf(((qy + 1.55f) / 2.5f) * 64.0f);
    const float fz = floorf(((qz + 1.25f) / 2.5f) * 64.0f);
    const bool inb = (fx >= 0.0f) & (fx < 64.0f) & (fy >= 0.0f) & (fy < 64.0f) &
                     (fz >= 0.0f) & (fz < 64.0f);
    bool mask = false;
    if (inb) {
        mask = __ldg(&density[(((int)fx) * GRD + (int)fy) * GRD + (int)fz]) > 0.5f;
    }
    mask_sh[tid] = mask ? 1 : 0;

    const float jit = __ldg(&jitter[ray * NS + tid]);
    const float zv  = (mask ? z : 0.0f) + jit * step;
    const float px = ox + zv * dx, py = oy + zv * dy, pz = oz + zv * dz;

    const unsigned bal = __ballot_sync(0xffffffffu, mask);

    if (bal) {
        // ---- phase A: h1 (fp32, constant-port W1) -> tf32 -> H1[sample][k] ----
        {
            uint32_t* row = H1u + tid * H1STR;
            #pragma unroll
            for (int kk = 0; kk < HD / 4; kk++) {
                uint4 u;
                {
                    const float4 q = *(const float4*)&c_W1q[16 * kk + 0];
                    u.x = f2tf32(fmaxf(fmaf(q.x, px, fmaf(q.y, py, fmaf(q.z, pz, q.w))), 0.0f));
                }
                {
                    const float4 q = *(const float4*)&c_W1q[16 * kk + 4];
                    u.y = f2tf32(fmaxf(fmaf(q.x, px, fmaf(q.y, py, fmaf(q.z, pz, q.w))), 0.0f));
                }
                {
                    const float4 q = *(const float4*)&c_W1q[16 * kk + 8];
                    u.z = f2tf32(fmaxf(fmaf(q.x, px, fmaf(q.y, py, fmaf(q.z, pz, q.w))), 0.0f));
                }
                {
                    const float4 q = *(const float4*)&c_W1q[16 * kk + 12];
                    u.w = f2tf32(fmaxf(fmaf(q.x, px, fmaf(q.y, py, fmaf(q.z, pz, q.w))), 0.0f));
                }
                ((uint4*)row)[kk] = u;
            }
        }
        __syncwarp();   // phase B reads only this warp's own 32 H1 rows

        // ---- phase B: warp MMA  D[32x64] = H1[32x64] * W2[64x64] ----
        float acc[2][8][4];
        #pragma unroll
        for (int mt = 0; mt < 2; mt++)
            #pragma unroll
            for (int nt = 0; nt < 8; nt++)
                #pragma unroll
                for (int e = 0; e < 4; e++) acc[mt][nt][e] = 0.0f;

        #pragma unroll
        for (int kt = 0; kt < 8; kt++) {
            const int kc = kt * 8 + tig;
            // A fragments for both m-tiles (rows sbase + mt*16 + g / +8)
            const uint32_t a00 = H1u[(sbase + g)      * H1STR + kc];
            const uint32_t a01 = H1u[(sbase + g + 8)  * H1STR + kc];
            const uint32_t a02 = H1u[(sbase + g)      * H1STR + kc + 4];
            const uint32_t a03 = H1u[(sbase + g + 8)  * H1STR + kc + 4];
            const uint32_t a10 = H1u[(sbase + g + 16) * H1STR + kc];
            const uint32_t a11 = H1u[(sbase + g + 24) * H1STR + kc];
            const uint32_t a12 = H1u[(sbase + g + 16) * H1STR + kc + 4];
            const uint32_t a13 = H1u[(sbase + g + 24) * H1STR + kc + 4];
            #pragma unroll
            for (int nt = 0; nt < 8; nt++) {
                const uint2 b = *(const uint2*)&Bfrag[((kt * 8 + nt) * 32 + lane) * 2];
                mma_tf32(acc[0][nt], a00, a01, a02, a03, b.x, b.y);
                mma_tf32(acc[1][nt], a10, a11, a12, a13, b.x, b.y);
            }
        }

        // ---- heads on C-fragments: thread owns cols {nt*8+2*tig, +1}, rows
        // slot0: sbase+g, slot1: sbase+g+8, slot2: sbase+g+16, slot3: sbase+g+24 ----
        float psig[4] = {0, 0, 0, 0}, pr[4] = {0, 0, 0, 0};
        float pg[4] = {0, 0, 0, 0},  pb[4] = {0, 0, 0, 0};
        #pragma unroll
        for (int nt = 0; nt < 8; nt++) {
            const int j0 = nt * 8 + 2 * tig;
            const float4 h0 = heads_s[j0];
            const float4 h1 = heads_s[j0 + 1];
            const float bb0 = b2s[j0], bb1 = b2s[j0 + 1];
            #pragma unroll
            for (int mt = 0; mt < 2; mt++) {
                const float* A = acc[mt][nt];
                const int sl = 2 * mt, sh = 2 * mt + 1;
                float v;
                v = fmaxf(A[0] + bb0, 0.0f);
                psig[sl] = fmaf(v, h0.x, psig[sl]); pr[sl] = fmaf(v, h0.y, pr[sl]);
                pg[sl]   = fmaf(v, h0.z, pg[sl]);   pb[sl] = fmaf(v, h0.w, pb[sl]);
                v = fmaxf(A[1] + bb1, 0.0f);
                psig[sl] = fmaf(v, h1.x, psig[sl]); pr[sl] = fmaf(v, h1.y, pr[sl]);
                pg[sl]   = fmaf(v, h1.z, pg[sl]);   pb[sl] = fmaf(v, h1.w, pb[sl]);
                v = fmaxf(A[2] + bb0, 0.0f);
                psig[sh] = fmaf(v, h0.x, psig[sh]); pr[sh] = fmaf(v, h0.y, pr[sh]);
                pg[sh]   = fmaf(v, h0.z, pg[sh]);   pb[sh] = fmaf(v, h0.w, pb[sh]);
                v = fmaxf(A[3] + bb1, 0.0f);
                psig[sh] = fmaf(v, h1.x, psig[sh]); pr[sh] = fmaf(v, h1.y, pr[sh]);
                pg[sh]   = fmaf(v, h1.z, pg[sh]);   pb[sh] = fmaf(v, h1.w, pb[sh]);
            }
        }
        // reduce over the 4 lanes of each group (tig dimension)
        #pragma unroll
        for (int m = 1; m < 4; m <<= 1) {
            #pragma unroll
            for (int s = 0; s < 4; s++) {
                psig[s] += __shfl_xor_sync(0xffffffffu, psig[s], m);
                pr[s]   += __shfl_xor_sync(0xffffffffu, pr[s],   m);
                pg[s]   += __shfl_xor_sync(0xffffffffu, pg[s],   m);
                pb[s]   += __shfl_xor_sync(0xffffffffu, pb[s],   m);
            }
        }
        if (tig == 0) {
            const float bs = __ldg(bsig);
            const float g0 = __ldg(&brgb[0]);
            const float g1 = __ldg(&brgb[1]);
            const float g2 = __ldg(&brgb[2]);
            #pragma unroll
            for (int s = 0; s < 4; s++) {
                const int samp = sbase + g + s * 8;
                float al = 0.f, q0 = 0.f, q1 = 0.f, q2 = 0.f;
                if (mask_sh[samp]) {
                    const float tau = fmaxf(psig[s] + bs, 0.0f) * step;
                    al = 1.0f - expf(-tau);
                    q0 = 1.0f / (1.0f + expf(-(pr[s] + g0)));
                    q1 = 1.0f / (1.0f + expf(-(pg[s] + g1)));
                    q2 = 1.0f / (1.0f + expf(-(pb[s] + g2)));
                }
                alpha_sh[samp] = al;
                r0s[samp] = q0; r1s[samp] = q1; r2s[samp] = q2;
            }
        }
    } else {
        alpha_sh[tid] = 0.f;
        r0s[tid] = 0.f; r1s[tid] = 0.f; r2s[tid] = 0.f;
    }

    __syncthreads();

    // ---- warp-parallel transmittance scan (warp 0, 4 samples/lane) ----
    if (tid < 32) {
        float a0 = alpha_sh[4 * tid + 0], a1 = alpha_sh[4 * tid + 1];
        float a2 = alpha_sh[4 * tid + 2], a3 = alpha_sh[4 * tid + 3];
        const float m0 = 1.0f - a0 + 1e-10f, m1 = 1.0f - a1 + 1e-10f;
        const float m2 = 1.0f - a2 + 1e-10f, m3 = 1.0f - a3 + 1e-10f;
        float inc = m0 * m1 * m2 * m3;
        #pragma unroll
        for (int off = 1; off < 32; off <<= 1) {
            const float v = __shfl_up_sync(0xffffffffu, inc, off);
            if (tid >= off) inc *= v;
        }
        float t = __shfl_up_sync(0xffffffffu, inc, 1);
        if (tid == 0) t = 1.0f;
        alpha_sh[4 * tid + 0] = a0 * t; t *= m0;
        alpha_sh[4 * tid + 1] = a1 * t; t *= m1;
        alpha_sh[4 * tid + 2] = a2 * t; t *= m2;
        alpha_sh[4 * tid + 3] = a3 * t; t *= m3;
        if (tid == 31) *nohit_sh = t;
    }
    __syncthreads();

    // ---- weighted color: warp butterfly + cross-warp combine in smem ----
    {
        const float w = alpha_sh[tid];
        float s0 = w * r0s[tid], s1 = w * r1s[tid], s2 = w * r2s[tid];
        #pragma unroll
        for (int m = 16; m > 0; m >>= 1) {
            s0 += __shfl_xor_sync(0xffffffffu, s0, m);
            s1 += __shfl_xor_sync(0xffffffffu, s1, m);
            s2 += __shfl_xor_sync(0xffffffffu, s2, m);
        }
        __syncthreads();               // r arrays reused below as partial store
        if (lane == 0) {
            r0s[wid] = s0; r1s[wid] = s1; r2s[wid] = s2;
        }
    }
    __syncthreads();
    if (tid == 0) {
        const float nh = *nohit_sh;    // white background
        out[ray * 3 + 0] = r0s[0] + r0s[1] + r0s[2] + r0s[3] + nh;
        out[ray * 3 + 1] = r1s[0] + r1s[1] + r1s[2] + r1s[3] + nh;
        out[ray * 3 + 2] = r2s[0] + r2s[1] + r2s[2] + r2s[3] + nh;
    }
}

extern "C" void kernel_launch(void* const* d_in, const int* in_sizes, int n_in,
                              void* d_out, int out_size) {
    const float* rays_o  = (const float*)d_in[0];
    const float* rays_d  = (const float*)d_in[1];
    const float* nearp   = (const float*)d_in[2];
    const float* farp    = (const float*)d_in[3];
    const float* jitter  = (const float*)d_in[4];
    const float* density = (const float*)d_in[5];
    const float* W1      = (const float*)d_in[6];
    const float* b1      = (const float*)d_in[7];
    const float* W2      = (const float*)d_in[8];
    const float* b2      = (const float*)d_in[9];
    const float* Wsig    = (const float*)d_in[10];
    const float* bsig    = (const float*)d_in[11];
    const float* Wrgb    = (const float*)d_in[12];
    const float* brgb    = (const float*)d_in[13];
    float* out = (float*)d_out;

    // pack W1/b1 into quads, then into __constant__ (all graph-capturable)
    prep_kernel<<<1, HD>>>(W1, b1);
    void* gp = nullptr;
    cudaGetSymbolAddress(&gp, g_W1q);
    cudaMemcpyToSymbolAsync(c_W1q, gp, 4 * HD * sizeof(float), 0,
                            cudaMemcpyDeviceToDevice, 0);

    static int attr_set = 0;
    if (!attr_set) {
        cudaFuncSetAttribute(raymarch_mma_kernel,
                             cudaFuncAttributeMaxDynamicSharedMemorySize, SMEM_SZ);
        attr_set = 1;
    }

    const int N = in_sizes[2];   // number of rays
    raymarch_mma_kernel<<<N, NS, SMEM_SZ>>>(rays_o, rays_d, nearp, farp, jitter, density,
                                            W2, b2, Wsig, bsig, Wrgb, brgb, out);
}